// round 1
// baseline (speedup 1.0000x reference)
#include <cuda_runtime.h>
#include <cuda_bf16.h>
#include <math.h>

// Problem constants
#define BB   2
#define SS   2048
#define HID  2048
#define HQ   16
#define HKV  4
#define DD   128
#define MM   (BB*SS)          // 4096 rows
#define QDIM (HQ*DD)          // 2048
#define KVDIM (HKV*DD)        // 512

// Scratch (device globals; allocation in kernel_launch is forbidden)
__device__ float g_h[MM*HID];       // rmsnorm output
__device__ float g_q[MM*QDIM];      // q after proj (+rope, in-place)
__device__ float g_k[MM*KVDIM];
__device__ float g_v[MM*KVDIM];
__device__ float g_att[MM*QDIM];    // attention output [B,S,Hq*D]

// ---------------------------------------------------------------------------
// RMSNorm: one block per row (2048 cols), 256 threads
// ---------------------------------------------------------------------------
__global__ void rmsnorm_kernel(const float* __restrict__ x,
                               const float* __restrict__ w,
                               float* __restrict__ out) {
    int row = blockIdx.x;
    int tid = threadIdx.x;
    const float4* xr = (const float4*)(x + (size_t)row * HID);
    float4 a = xr[tid];
    float4 b = xr[tid + 256];
    float ss = a.x*a.x + a.y*a.y + a.z*a.z + a.w*a.w
             + b.x*b.x + b.y*b.y + b.z*b.z + b.w*b.w;
    // warp reduce
    #pragma unroll
    for (int off = 16; off > 0; off >>= 1)
        ss += __shfl_xor_sync(0xffffffffu, ss, off);
    __shared__ float sred[8];
    __shared__ float sinv;
    if ((tid & 31) == 0) sred[tid >> 5] = ss;
    __syncthreads();
    if (tid == 0) {
        float t = 0.f;
        #pragma unroll
        for (int i = 0; i < 8; i++) t += sred[i];
        sinv = rsqrtf(t / (float)HID + 1e-6f);
    }
    __syncthreads();
    float inv = sinv;
    const float4* wr = (const float4*)w;
    float4 wa = wr[tid], wb = wr[tid + 256];
    float4* orow = (float4*)(out + (size_t)row * HID);
    float4 oa, ob;
    oa.x = a.x*inv*wa.x; oa.y = a.y*inv*wa.y; oa.z = a.z*inv*wa.z; oa.w = a.w*inv*wa.w;
    ob.x = b.x*inv*wb.x; ob.y = b.y*inv*wb.y; ob.z = b.z*inv*wb.z; ob.w = b.w*inv*wb.w;
    orow[tid] = oa;
    orow[tid + 256] = ob;
}

// ---------------------------------------------------------------------------
// SGEMM (NT):  C[m][n] = sum_k A[m][k] * B[n][k] + bias[n]
// 128x128 tile, K-step 8, 256 threads, 8x8 per-thread microtile
// Shapes here are always divisible by tiles -> no bounds checks.
// ---------------------------------------------------------------------------
__global__ __launch_bounds__(256, 2)
void sgemm_nt(const float* __restrict__ A, const float* __restrict__ Bm,
              const float* __restrict__ bias, float* __restrict__ C,
              int M, int N, int K) {
    __shared__ float As[8][128];
    __shared__ float Bs[8][128];
    int tid = threadIdx.x;
    int brow = blockIdx.y * 128;
    int bcol = blockIdx.x * 128;
    int tx = tid & 15;        // 0..15 -> col group
    int ty = tid >> 4;        // 0..15 -> row group
    int lrow = tid >> 1;      // 0..127
    int lk4  = (tid & 1) * 4; // 0 or 4

    float acc[8][8];
    #pragma unroll
    for (int i = 0; i < 8; i++)
        #pragma unroll
        for (int j = 0; j < 8; j++) acc[i][j] = 0.f;

    const float* Aptr = A + (size_t)(brow + lrow) * K + lk4;
    const float* Bptr = Bm + (size_t)(bcol + lrow) * K + lk4;

    for (int k0 = 0; k0 < K; k0 += 8) {
        float4 av = *(const float4*)(Aptr + k0);
        float4 bv = *(const float4*)(Bptr + k0);
        __syncthreads();
        As[lk4+0][lrow] = av.x; As[lk4+1][lrow] = av.y;
        As[lk4+2][lrow] = av.z; As[lk4+3][lrow] = av.w;
        Bs[lk4+0][lrow] = bv.x; Bs[lk4+1][lrow] = bv.y;
        Bs[lk4+2][lrow] = bv.z; Bs[lk4+3][lrow] = bv.w;
        __syncthreads();
        #pragma unroll
        for (int kk = 0; kk < 8; kk++) {
            float a[8], bfr[8];
            #pragma unroll
            for (int i = 0; i < 8; i++) a[i] = As[kk][ty*8 + i];
            #pragma unroll
            for (int j = 0; j < 8; j++) bfr[j] = Bs[kk][tx*8 + j];
            #pragma unroll
            for (int i = 0; i < 8; i++)
                #pragma unroll
                for (int j = 0; j < 8; j++)
                    acc[i][j] += a[i] * bfr[j];
        }
    }

    #pragma unroll
    for (int i = 0; i < 8; i++) {
        int r = brow + ty*8 + i;
        #pragma unroll
        for (int j = 0; j < 8; j++) {
            int c = bcol + tx*8 + j;
            float vv = acc[i][j];
            if (bias) vv += bias[c];
            C[(size_t)r * N + c] = vv;
        }
    }
}

// ---------------------------------------------------------------------------
// RoPE (rotate-half), in place. layout [B][S][nHeads*128]
// ---------------------------------------------------------------------------
__global__ void rope_kernel(float* __restrict__ t, int nHeads, int total) {
    int idx = blockIdx.x * blockDim.x + threadIdx.x;
    if (idx >= total) return;
    int j = idx & 63;
    int h = (idx >> 6) % nHeads;
    int s = (idx / (64 * nHeads)) % SS;
    int b = idx / (64 * nHeads * SS);
    // inv_freq = 10000^(-(2j)/128)
    float inv_freq = expf(-((float)(2*j) / 128.f) * logf(10000.f));
    float ang = (float)s * inv_freq;
    float c, sn;
    sincosf(ang, &sn, &c);
    float* base = t + ((size_t)(b*SS + s) * nHeads + h) * 128;
    float a0 = base[j];
    float a1 = base[j + 64];
    base[j]      = a0 * c - a1 * sn;
    base[j + 64] = a1 * c + a0 * sn;
}

// ---------------------------------------------------------------------------
// Causal grouped flash attention, fp32.
// grid (S/32, HQ, B), 256 threads. BM=BN=32.
// q layout [B][S][Hq*128], k/v layout [B][S][Hkv*128]
// out -> g_att [B][S][Hq*128]
// ---------------------------------------------------------------------------
__global__ __launch_bounds__(256, 4)
void attn_kernel(const float* __restrict__ q, const float* __restrict__ k,
                 const float* __restrict__ v, float* __restrict__ out) {
    int qt = blockIdx.x;          // query tile
    int hq = blockIdx.y;
    int b  = blockIdx.z;
    int g  = hq >> 2;             // kv head (rep = 4)
    int q0 = qt * 32;

    __shared__ float Qs[32][129];
    __shared__ float KVs[32][129];

    int tid = threadIdx.x;
    int tx = tid & 31;   // lane
    int ty = tid >> 5;   // warp 0..7

    // load Q tile
    for (int i = tid; i < 32*32; i += 256) {
        int r = i >> 5;
        int c4 = (i & 31) * 4;
        float4 vq = *(const float4*)(q + (size_t)(b*SS + q0 + r) * QDIM + hq*128 + c4);
        Qs[r][c4+0] = vq.x; Qs[r][c4+1] = vq.y; Qs[r][c4+2] = vq.z; Qs[r][c4+3] = vq.w;
    }

    float m[4], l[4], acc[4][4];
    #pragma unroll
    for (int rr = 0; rr < 4; rr++) {
        m[rr] = -INFINITY; l[rr] = 0.f;
        #pragma unroll
        for (int cc = 0; cc < 4; cc++) acc[rr][cc] = 0.f;
    }

    const float scale = 0.08838834764831845f;  // 1/sqrt(128)

    for (int kt = 0; kt <= qt; kt++) {
        int n0 = kt * 32;
        __syncthreads();
        // load K tile
        for (int i = tid; i < 32*32; i += 256) {
            int r = i >> 5;
            int c4 = (i & 31) * 4;
            float4 vk = *(const float4*)(k + (size_t)(b*SS + n0 + r) * KVDIM + g*128 + c4);
            KVs[r][c4+0] = vk.x; KVs[r][c4+1] = vk.y; KVs[r][c4+2] = vk.z; KVs[r][c4+3] = vk.w;
        }
        __syncthreads();

        float p[4];
        #pragma unroll
        for (int rr = 0; rr < 4; rr++) {
            int row = rr*8 + ty;
            float sc = 0.f;
            #pragma unroll 8
            for (int d = 0; d < 128; d++)
                sc += Qs[row][d] * KVs[tx][d];
            sc *= scale;
            int qi = q0 + row;
            int kj = n0 + tx;
            if (kj > qi) sc = -1e30f;
            // row max
            float mx = sc;
            #pragma unroll
            for (int off = 16; off > 0; off >>= 1)
                mx = fmaxf(mx, __shfl_xor_sync(0xffffffffu, mx, off));
            float mnew = fmaxf(m[rr], mx);
            float alpha = __expf(m[rr] - mnew);
            float pv = __expf(sc - mnew);
            float rs = pv;
            #pragma unroll
            for (int off = 16; off > 0; off >>= 1)
                rs += __shfl_xor_sync(0xffffffffu, rs, off);
            l[rr] = l[rr] * alpha + rs;
            m[rr] = mnew;
            p[rr] = pv;
            #pragma unroll
            for (int cc = 0; cc < 4; cc++) acc[rr][cc] *= alpha;
        }

        __syncthreads();
        // load V tile (reuse KVs)
        for (int i = tid; i < 32*32; i += 256) {
            int r = i >> 5;
            int c4 = (i & 31) * 4;
            float4 vv = *(const float4*)(v + (size_t)(b*SS + n0 + r) * KVDIM + g*128 + c4);
            KVs[r][c4+0] = vv.x; KVs[r][c4+1] = vv.y; KVs[r][c4+2] = vv.z; KVs[r][c4+3] = vv.w;
        }
        __syncthreads();

        // P @ V : p[rr] lives in lane j for key j (same warp owns the row)
        #pragma unroll 8
        for (int j = 0; j < 32; j++) {
            float v0 = KVs[j][tx];
            float v1 = KVs[j][tx + 32];
            float v2 = KVs[j][tx + 64];
            float v3 = KVs[j][tx + 96];
            #pragma unroll
            for (int rr = 0; rr < 4; rr++) {
                float pj = __shfl_sync(0xffffffffu, p[rr], j);
                acc[rr][0] += pj * v0;
                acc[rr][1] += pj * v1;
                acc[rr][2] += pj * v2;
                acc[rr][3] += pj * v3;
            }
        }
    }

    // write output
    #pragma unroll
    for (int rr = 0; rr < 4; rr++) {
        int row = rr*8 + ty;
        float invl = 1.f / l[rr];
        float* ob = out + (size_t)(b*SS + q0 + row) * QDIM + hq*128;
        #pragma unroll
        for (int cc = 0; cc < 4; cc++)
            ob[tx + cc*32] = acc[rr][cc] * invl;
    }
}

// ---------------------------------------------------------------------------
extern "C" void kernel_launch(void* const* d_in, const int* in_sizes, int n_in,
                              void* d_out, int out_size) {
    const float* x  = (const float*)d_in[0];
    const float* qp = (const float*)d_in[1];
    const float* kp = (const float*)d_in[2];
    const float* vp = (const float*)d_in[3];
    const float* qb = (const float*)d_in[4];
    const float* kb = (const float*)d_in[5];
    const float* vb = (const float*)d_in[6];
    const float* op = (const float*)d_in[7];
    const float* lw = (const float*)d_in[8];
    float* out = (float*)d_out;

    float *h, *q, *k, *v, *att;
    cudaGetSymbolAddress((void**)&h,   g_h);
    cudaGetSymbolAddress((void**)&q,   g_q);
    cudaGetSymbolAddress((void**)&k,   g_k);
    cudaGetSymbolAddress((void**)&v,   g_v);
    cudaGetSymbolAddress((void**)&att, g_att);

    // 1. RMSNorm
    rmsnorm_kernel<<<MM, 256>>>(x, lw, h);

    // 2. QKV projections (+bias)
    {
        dim3 gq(QDIM/128, MM/128);
        sgemm_nt<<<gq, 256>>>(h, qp, qb, q, MM, QDIM, HID);
        dim3 gkv(KVDIM/128, MM/128);
        sgemm_nt<<<gkv, 256>>>(h, kp, kb, k, MM, KVDIM, HID);
        sgemm_nt<<<gkv, 256>>>(h, vp, vb, v, MM, KVDIM, HID);
    }

    // 3. RoPE on q and k
    {
        int totq = BB * SS * HQ * 64;
        rope_kernel<<<(totq + 255)/256, 256>>>(q, HQ, totq);
        int totk = BB * SS * HKV * 64;
        rope_kernel<<<(totk + 255)/256, 256>>>(k, HKV, totk);
    }

    // 4. Causal grouped flash attention
    {
        dim3 ga(SS/32, HQ, BB);
        attn_kernel<<<ga, 256>>>(q, k, v, att);
    }

    // 5. Output projection (no bias)
    {
        dim3 go(HID/128, MM/128);
        sgemm_nt<<<go, 256>>>(att, op, nullptr, out, MM, HID, HID);
    }
}

// round 2
// speedup vs baseline: 1.0088x; 1.0088x over previous
#include <cuda_runtime.h>
#include <cuda_bf16.h>
#include <math.h>

// Problem constants
#define BB   2
#define SS   2048
#define HID  2048
#define HQ   16
#define HKV  4
#define DD   128
#define MM   (BB*SS)          // 4096 rows
#define QDIM (HQ*DD)          // 2048
#define KVDIM (HKV*DD)        // 512

// Scratch (device globals; allocation in kernel_launch is forbidden)
__device__ float g_h[MM*HID];       // rmsnorm output
__device__ float g_q[MM*QDIM];      // q after proj (+rope, in-place)
__device__ float g_k[MM*KVDIM];
__device__ float g_v[MM*KVDIM];
__device__ float g_att[MM*QDIM];    // attention output [B,S,Hq*D]

// ---------------------------------------------------------------------------
// RMSNorm: one block per row (2048 cols), 256 threads
// ---------------------------------------------------------------------------
__global__ void rmsnorm_kernel(const float* __restrict__ x,
                               const float* __restrict__ w,
                               float* __restrict__ out) {
    int row = blockIdx.x;
    int tid = threadIdx.x;
    const float4* xr = (const float4*)(x + (size_t)row * HID);
    float4 a = xr[tid];
    float4 b = xr[tid + 256];
    float ss = a.x*a.x + a.y*a.y + a.z*a.z + a.w*a.w
             + b.x*b.x + b.y*b.y + b.z*b.z + b.w*b.w;
    // warp reduce
    #pragma unroll
    for (int off = 16; off > 0; off >>= 1)
        ss += __shfl_xor_sync(0xffffffffu, ss, off);
    __shared__ float sred[8];
    __shared__ float sinv;
    if ((tid & 31) == 0) sred[tid >> 5] = ss;
    __syncthreads();
    if (tid == 0) {
        float t = 0.f;
        #pragma unroll
        for (int i = 0; i < 8; i++) t += sred[i];
        sinv = rsqrtf(t / (float)HID + 1e-6f);
    }
    __syncthreads();
    float inv = sinv;
    const float4* wr = (const float4*)w;
    float4 wa = wr[tid], wb = wr[tid + 256];
    float4* orow = (float4*)(out + (size_t)row * HID);
    float4 oa, ob;
    oa.x = a.x*inv*wa.x; oa.y = a.y*inv*wa.y; oa.z = a.z*inv*wa.z; oa.w = a.w*inv*wa.w;
    ob.x = b.x*inv*wb.x; ob.y = b.y*inv*wb.y; ob.z = b.z*inv*wb.z; ob.w = b.w*inv*wb.w;
    orow[tid] = oa;
    orow[tid + 256] = ob;
}

// ---------------------------------------------------------------------------
// SGEMM (NT):  C[m][n] = sum_k A[m][k] * B[n][k] + bias[n]
// 128x128 tile, K-step 8, 256 threads, 8x8 per-thread microtile
// Shapes here are always divisible by tiles -> no bounds checks.
// ---------------------------------------------------------------------------
__global__ __launch_bounds__(256, 2)
void sgemm_nt(const float* __restrict__ A, const float* __restrict__ Bm,
              const float* __restrict__ bias, float* __restrict__ C,
              int M, int N, int K) {
    __shared__ float As[8][128];
    __shared__ float Bs[8][128];
    int tid = threadIdx.x;
    int brow = blockIdx.y * 128;
    int bcol = blockIdx.x * 128;
    int tx = tid & 15;        // 0..15 -> col group
    int ty = tid >> 4;        // 0..15 -> row group
    int lrow = tid >> 1;      // 0..127
    int lk4  = (tid & 1) * 4; // 0 or 4

    float acc[8][8];
    #pragma unroll
    for (int i = 0; i < 8; i++)
        #pragma unroll
        for (int j = 0; j < 8; j++) acc[i][j] = 0.f;

    const float* Aptr = A + (size_t)(brow + lrow) * K + lk4;
    const float* Bptr = Bm + (size_t)(bcol + lrow) * K + lk4;

    for (int k0 = 0; k0 < K; k0 += 8) {
        float4 av = *(const float4*)(Aptr + k0);
        float4 bv = *(const float4*)(Bptr + k0);
        __syncthreads();
        As[lk4+0][lrow] = av.x; As[lk4+1][lrow] = av.y;
        As[lk4+2][lrow] = av.z; As[lk4+3][lrow] = av.w;
        Bs[lk4+0][lrow] = bv.x; Bs[lk4+1][lrow] = bv.y;
        Bs[lk4+2][lrow] = bv.z; Bs[lk4+3][lrow] = bv.w;
        __syncthreads();
        #pragma unroll
        for (int kk = 0; kk < 8; kk++) {
            float a[8], bfr[8];
            #pragma unroll
            for (int i = 0; i < 8; i++) a[i] = As[kk][ty*8 + i];
            #pragma unroll
            for (int j = 0; j < 8; j++) bfr[j] = Bs[kk][tx*8 + j];
            #pragma unroll
            for (int i = 0; i < 8; i++)
                #pragma unroll
                for (int j = 0; j < 8; j++)
                    acc[i][j] += a[i] * bfr[j];
        }
    }

    #pragma unroll
    for (int i = 0; i < 8; i++) {
        int r = brow + ty*8 + i;
        #pragma unroll
        for (int j = 0; j < 8; j++) {
            int c = bcol + tx*8 + j;
            float vv = acc[i][j];
            if (bias) vv += bias[c];
            C[(size_t)r * N + c] = vv;
        }
    }
}

// ---------------------------------------------------------------------------
// RoPE (rotate-half), in place. layout [B][S][nHeads*128]
// ---------------------------------------------------------------------------
__global__ void rope_kernel(float* __restrict__ t, int nHeads, int total) {
    int idx = blockIdx.x * blockDim.x + threadIdx.x;
    if (idx >= total) return;
    int j = idx & 63;
    int h = (idx >> 6) % nHeads;
    int s = (idx / (64 * nHeads)) % SS;
    int b = idx / (64 * nHeads * SS);
    // inv_freq = 10000^(-(2j)/128)
    float inv_freq = expf(-((float)(2*j) / 128.f) * logf(10000.f));
    float ang = (float)s * inv_freq;
    float c, sn;
    sincosf(ang, &sn, &c);
    float* base = t + ((size_t)(b*SS + s) * nHeads + h) * 128;
    float a0 = base[j];
    float a1 = base[j + 64];
    base[j]      = a0 * c - a1 * sn;
    base[j + 64] = a1 * c + a0 * sn;
}

// ---------------------------------------------------------------------------
// Causal grouped flash attention, fp32.
// grid (S/32, HQ, B), 256 threads. BM=BN=32.
// q layout [B][S][Hq*128], k/v layout [B][S][Hkv*128]
// out -> g_att [B][S][Hq*128]
// ---------------------------------------------------------------------------
__global__ __launch_bounds__(256, 4)
void attn_kernel(const float* __restrict__ q, const float* __restrict__ k,
                 const float* __restrict__ v, float* __restrict__ out) {
    int qt = blockIdx.x;          // query tile
    int hq = blockIdx.y;
    int b  = blockIdx.z;
    int g  = hq >> 2;             // kv head (rep = 4)
    int q0 = qt * 32;

    __shared__ float Qs[32][129];
    __shared__ float KVs[32][129];

    int tid = threadIdx.x;
    int tx = tid & 31;   // lane
    int ty = tid >> 5;   // warp 0..7

    // load Q tile
    for (int i = tid; i < 32*32; i += 256) {
        int r = i >> 5;
        int c4 = (i & 31) * 4;
        float4 vq = *(const float4*)(q + (size_t)(b*SS + q0 + r) * QDIM + hq*128 + c4);
        Qs[r][c4+0] = vq.x; Qs[r][c4+1] = vq.y; Qs[r][c4+2] = vq.z; Qs[r][c4+3] = vq.w;
    }

    float m[4], l[4], acc[4][4];
    #pragma unroll
    for (int rr = 0; rr < 4; rr++) {
        m[rr] = -INFINITY; l[rr] = 0.f;
        #pragma unroll
        for (int cc = 0; cc < 4; cc++) acc[rr][cc] = 0.f;
    }

    const float scale = 0.08838834764831845f;  // 1/sqrt(128)

    for (int kt = 0; kt <= qt; kt++) {
        int n0 = kt * 32;
        __syncthreads();
        // load K tile
        for (int i = tid; i < 32*32; i += 256) {
            int r = i >> 5;
            int c4 = (i & 31) * 4;
            float4 vk = *(const float4*)(k + (size_t)(b*SS + n0 + r) * KVDIM + g*128 + c4);
            KVs[r][c4+0] = vk.x; KVs[r][c4+1] = vk.y; KVs[r][c4+2] = vk.z; KVs[r][c4+3] = vk.w;
        }
        __syncthreads();

        float p[4];
        #pragma unroll
        for (int rr = 0; rr < 4; rr++) {
            int row = rr*8 + ty;
            float sc = 0.f;
            #pragma unroll 8
            for (int d = 0; d < 128; d++)
                sc += Qs[row][d] * KVs[tx][d];
            sc *= scale;
            int qi = q0 + row;
            int kj = n0 + tx;
            if (kj > qi) sc = -1e30f;
            // row max
            float mx = sc;
            #pragma unroll
            for (int off = 16; off > 0; off >>= 1)
                mx = fmaxf(mx, __shfl_xor_sync(0xffffffffu, mx, off));
            float mnew = fmaxf(m[rr], mx);
            float alpha = __expf(m[rr] - mnew);
            float pv = __expf(sc - mnew);
            float rs = pv;
            #pragma unroll
            for (int off = 16; off > 0; off >>= 1)
                rs += __shfl_xor_sync(0xffffffffu, rs, off);
            l[rr] = l[rr] * alpha + rs;
            m[rr] = mnew;
            p[rr] = pv;
            #pragma unroll
            for (int cc = 0; cc < 4; cc++) acc[rr][cc] *= alpha;
        }

        __syncthreads();
        // load V tile (reuse KVs)
        for (int i = tid; i < 32*32; i += 256) {
            int r = i >> 5;
            int c4 = (i & 31) * 4;
            float4 vv = *(const float4*)(v + (size_t)(b*SS + n0 + r) * KVDIM + g*128 + c4);
            KVs[r][c4+0] = vv.x; KVs[r][c4+1] = vv.y; KVs[r][c4+2] = vv.z; KVs[r][c4+3] = vv.w;
        }
        __syncthreads();

        // P @ V : p[rr] lives in lane j for key j (same warp owns the row)
        #pragma unroll 8
        for (int j = 0; j < 32; j++) {
            float v0 = KVs[j][tx];
            float v1 = KVs[j][tx + 32];
            float v2 = KVs[j][tx + 64];
            float v3 = KVs[j][tx + 96];
            #pragma unroll
            for (int rr = 0; rr < 4; rr++) {
                float pj = __shfl_sync(0xffffffffu, p[rr], j);
                acc[rr][0] += pj * v0;
                acc[rr][1] += pj * v1;
                acc[rr][2] += pj * v2;
                acc[rr][3] += pj * v3;
            }
        }
    }

    // write output
    #pragma unroll
    for (int rr = 0; rr < 4; rr++) {
        int row = rr*8 + ty;
        float invl = 1.f / l[rr];
        float* ob = out + (size_t)(b*SS + q0 + row) * QDIM + hq*128;
        #pragma unroll
        for (int cc = 0; cc < 4; cc++)
            ob[tx + cc*32] = acc[rr][cc] * invl;
    }
}

// ---------------------------------------------------------------------------
extern "C" void kernel_launch(void* const* d_in, const int* in_sizes, int n_in,
                              void* d_out, int out_size) {
    const float* x  = (const float*)d_in[0];
    const float* qp = (const float*)d_in[1];
    const float* kp = (const float*)d_in[2];
    const float* vp = (const float*)d_in[3];
    const float* qb = (const float*)d_in[4];
    const float* kb = (const float*)d_in[5];
    const float* vb = (const float*)d_in[6];
    const float* op = (const float*)d_in[7];
    const float* lw = (const float*)d_in[8];
    float* out = (float*)d_out;

    float *h, *q, *k, *v, *att;
    cudaGetSymbolAddress((void**)&h,   g_h);
    cudaGetSymbolAddress((void**)&q,   g_q);
    cudaGetSymbolAddress((void**)&k,   g_k);
    cudaGetSymbolAddress((void**)&v,   g_v);
    cudaGetSymbolAddress((void**)&att, g_att);

    // 1. RMSNorm
    rmsnorm_kernel<<<MM, 256>>>(x, lw, h);

    // 2. QKV projections (+bias)
    {
        dim3 gq(QDIM/128, MM/128);
        sgemm_nt<<<gq, 256>>>(h, qp, qb, q, MM, QDIM, HID);
        dim3 gkv(KVDIM/128, MM/128);
        sgemm_nt<<<gkv, 256>>>(h, kp, kb, k, MM, KVDIM, HID);
        sgemm_nt<<<gkv, 256>>>(h, vp, vb, v, MM, KVDIM, HID);
    }

    // 3. RoPE on q and k
    {
        int totq = BB * SS * HQ * 64;
        rope_kernel<<<(totq + 255)/256, 256>>>(q, HQ, totq);
        int totk = BB * SS * HKV * 64;
        rope_kernel<<<(totk + 255)/256, 256>>>(k, HKV, totk);
    }

    // 4. Causal grouped flash attention
    {
        dim3 ga(SS/32, HQ, BB);
        attn_kernel<<<ga, 256>>>(q, k, v, att);
    }

    // 5. Output projection (no bias)
    {
        dim3 go(HID/128, MM/128);
        sgemm_nt<<<go, 256>>>(att, op, nullptr, out, MM, HID, HID);
    }
}

// round 5
// speedup vs baseline: 1.4543x; 1.4416x over previous
#include <cuda_runtime.h>
#include <cuda_bf16.h>
#include <cstdint>
#include <math.h>

typedef __nv_bfloat16 bf16;

#define BB   2
#define SS   2048
#define HID  2048
#define HQ   16
#define HKV  4
#define MM   (BB*SS)          // 4096
#define QDIM 2048
#define KVDIM 512

// ---------------- scratch ----------------
__device__ __align__(16) bf16 g_h_hi[MM*HID];
__device__ __align__(16) bf16 g_h_lo[MM*HID];
__device__ __align__(16) bf16 g_wq_hi[QDIM*HID];
__device__ __align__(16) bf16 g_wq_lo[QDIM*HID];
__device__ __align__(16) bf16 g_wk_hi[KVDIM*HID];
__device__ __align__(16) bf16 g_wk_lo[KVDIM*HID];
__device__ __align__(16) bf16 g_wv_hi[KVDIM*HID];
__device__ __align__(16) bf16 g_wv_lo[KVDIM*HID];
__device__ __align__(16) bf16 g_wo_hi[HID*QDIM];
__device__ __align__(16) bf16 g_wo_lo[HID*QDIM];
__device__ __align__(16) float g_q[MM*QDIM];
__device__ __align__(16) float g_k[MM*KVDIM];
__device__ __align__(16) float g_v[MM*KVDIM];
__device__ __align__(16) float g_att[MM*QDIM];
__device__ __align__(16) bf16 g_att_hi[MM*QDIM];
__device__ __align__(16) bf16 g_att_lo[MM*QDIM];

// ---------------- helpers ----------------
__device__ __forceinline__ uint32_t smem_u32(const void* p) {
    uint32_t a;
    asm("{ .reg .u64 t; cvta.to.shared.u64 t, %1; cvt.u32.u64 %0, t; }" : "=r"(a) : "l"(p));
    return a;
}
__device__ __forceinline__ void cp16(uint32_t dst, const void* src) {
    asm volatile("cp.async.cg.shared.global [%0], [%1], 16;" :: "r"(dst), "l"(src));
}
#define CP_COMMIT() asm volatile("cp.async.commit_group;" ::: "memory")
#define CP_WAIT(n)  asm volatile("cp.async.wait_group %0;" :: "n"(n) : "memory")

__device__ __forceinline__ uint32_t lds32(uint32_t a) {
    uint32_t v;
    asm("ld.shared.b32 %0, [%1];" : "=r"(v) : "r"(a));
    return v;
}
__device__ __forceinline__ void mma16816(float* d, const uint32_t* a, const uint32_t* b) {
    asm volatile("mma.sync.aligned.m16n8k16.row.col.f32.bf16.bf16.f32 "
        "{%0,%1,%2,%3}, {%4,%5,%6,%7}, {%8,%9}, {%0,%1,%2,%3};"
        : "+f"(d[0]), "+f"(d[1]), "+f"(d[2]), "+f"(d[3])
        : "r"(a[0]), "r"(a[1]), "r"(a[2]), "r"(a[3]), "r"(b[0]), "r"(b[1]));
}

// ---------------------------------------------------------------------------
// RMSNorm -> bf16 hi/lo   (round-1 rmsnorm with hi/lo stores)
// ---------------------------------------------------------------------------
__global__ void rmsnorm_kernel(const float* __restrict__ x,
                               const float* __restrict__ w,
                               bf16* __restrict__ ohi, bf16* __restrict__ olo) {
    int row = blockIdx.x;
    int tid = threadIdx.x;
    const float4* xr = (const float4*)(x + (size_t)row * HID);
    float4 a = xr[tid];
    float4 b = xr[tid + 256];
    float ss = a.x*a.x + a.y*a.y + a.z*a.z + a.w*a.w
             + b.x*b.x + b.y*b.y + b.z*b.z + b.w*b.w;
    #pragma unroll
    for (int off = 16; off > 0; off >>= 1)
        ss += __shfl_xor_sync(0xffffffffu, ss, off);
    __shared__ float sred[8];
    __shared__ float sinv;
    if ((tid & 31) == 0) sred[tid >> 5] = ss;
    __syncthreads();
    if (tid == 0) {
        float t = 0.f;
        #pragma unroll
        for (int i = 0; i < 8; i++) t += sred[i];
        sinv = rsqrtf(t / (float)HID + 1e-6f);
    }
    __syncthreads();
    float inv = sinv;
    const float4* wr = (const float4*)w;
    float4 wa = wr[tid], wb = wr[tid + 256];
    float va[8] = { a.x*inv*wa.x, a.y*inv*wa.y, a.z*inv*wa.z, a.w*inv*wa.w,
                    b.x*inv*wb.x, b.y*inv*wb.y, b.z*inv*wb.z, b.w*inv*wb.w };
    size_t base0 = (size_t)row * HID + tid*4;
    size_t base1 = (size_t)row * HID + (tid+256)*4;
    #pragma unroll
    for (int i = 0; i < 4; i++) {
        bf16 h0 = __float2bfloat16(va[i]);
        ohi[base0+i] = h0;
        olo[base0+i] = __float2bfloat16(va[i] - __bfloat162float(h0));
        bf16 h1 = __float2bfloat16(va[4+i]);
        ohi[base1+i] = h1;
        olo[base1+i] = __float2bfloat16(va[4+i] - __bfloat162float(h1));
    }
}

// ---------------------------------------------------------------------------
// split fp32 -> bf16 hi/lo
// ---------------------------------------------------------------------------
__global__ void split_kernel(const float* __restrict__ in, bf16* __restrict__ hi,
                             bf16* __restrict__ lo, int n4) {
    int i = blockIdx.x * 256 + threadIdx.x;
    if (i >= n4) return;
    float4 v = ((const float4*)in)[i];
    bf16 h0 = __float2bfloat16(v.x), h1 = __float2bfloat16(v.y);
    bf16 h2 = __float2bfloat16(v.z), h3 = __float2bfloat16(v.w);
    __nv_bfloat162 hh0; hh0.x = h0; hh0.y = h1;
    __nv_bfloat162 hh1; hh1.x = h2; hh1.y = h3;
    __nv_bfloat162 ll0, ll1;
    ll0.x = __float2bfloat16(v.x - __bfloat162float(h0));
    ll0.y = __float2bfloat16(v.y - __bfloat162float(h1));
    ll1.x = __float2bfloat16(v.z - __bfloat162float(h2));
    ll1.y = __float2bfloat16(v.w - __bfloat162float(h3));
    ((__nv_bfloat162*)hi)[i*2+0] = hh0;
    ((__nv_bfloat162*)hi)[i*2+1] = hh1;
    ((__nv_bfloat162*)lo)[i*2+0] = ll0;
    ((__nv_bfloat162*)lo)[i*2+1] = ll1;
}

// ---------------------------------------------------------------------------
// HMMA GEMM (NT): C[m][n] = sum_k A[m][k]*B[n][k] + bias[n], K=2048.
// 3-term hi/lo split. Tile 128x128, K-chunk 64, cp.async double-buffered.
// 256 threads, warp grid 2(m) x 4(n), warp tile 64x32.
// smem: 2 stages x (Ah,Al,Bh,Bl each 128rows x 128B SW128) = 131072 B.
// ---------------------------------------------------------------------------
__global__ __launch_bounds__(256, 1)
void gemm_mma(const bf16* __restrict__ Ah, const bf16* __restrict__ Al,
              const bf16* __restrict__ Bh, const bf16* __restrict__ Bl,
              const float* __restrict__ bias, float* __restrict__ Cf, int N) {
    extern __shared__ __align__(128) char sm[];
    uint32_t sb = smem_u32(sm);
    int tid = threadIdx.x;
    int w = tid >> 5, lane = tid & 31, g = lane >> 2, tig = lane & 3;
    int wm = w & 1, wn = w >> 1;
    int brow = blockIdx.y * 128, bcol = blockIdx.x * 128;

    float acc[4][4][4];
    #pragma unroll
    for (int a = 0; a < 4; a++)
        #pragma unroll
        for (int b = 0; b < 4; b++)
            #pragma unroll
            for (int c = 0; c < 4; c++) acc[a][b][c] = 0.f;

    auto load_stage = [&](int s, int ck) {
        #pragma unroll
        for (int mat = 0; mat < 4; mat++) {
            const bf16* base = (mat == 0) ? Ah : (mat == 1) ? Al : (mat == 2) ? Bh : Bl;
            int ro = (mat < 2) ? brow : bcol;
            #pragma unroll
            for (int i = 0; i < 4; i++) {
                int id = i*256 + tid;
                int r = id >> 3, c = id & 7;
                cp16(sb + s*65536 + mat*16384 + r*128 + (((uint32_t)c*16) ^ ((uint32_t)(r&7)*16)),
                     base + (size_t)(ro + r)*2048 + ck*64 + c*8);
            }
        }
    };

    load_stage(0, 0);
    CP_COMMIT();

    for (int ck = 0; ck < 32; ck++) {
        if (ck + 1 < 32) { load_stage((ck+1)&1, ck+1); CP_COMMIT(); CP_WAIT(1); }
        else             { CP_WAIT(0); }
        __syncthreads();
        uint32_t tb = sb + (ck&1)*65536;
        uint32_t swz = (uint32_t)g*16;
        #pragma unroll
        for (int ks = 0; ks < 4; ks++) {
            uint32_t o0 = (uint32_t)(32*ks + 4*tig);
            uint32_t ah[4][4], al[4][4];
            #pragma unroll
            for (int mb = 0; mb < 4; mb++) {
                uint32_t r0 = (uint32_t)(wm*64 + mb*16 + g)*128;
                uint32_t r1 = r0 + 8*128;
                ah[mb][0] = lds32(tb + r0 + (o0^swz));
                ah[mb][1] = lds32(tb + r1 + (o0^swz));
                ah[mb][2] = lds32(tb + r0 + ((o0+16)^swz));
                ah[mb][3] = lds32(tb + r1 + ((o0+16)^swz));
                al[mb][0] = lds32(tb + 16384 + r0 + (o0^swz));
                al[mb][1] = lds32(tb + 16384 + r1 + (o0^swz));
                al[mb][2] = lds32(tb + 16384 + r0 + ((o0+16)^swz));
                al[mb][3] = lds32(tb + 16384 + r1 + ((o0+16)^swz));
            }
            uint32_t bh[4][2], bl[4][2];
            #pragma unroll
            for (int nb = 0; nb < 4; nb++) {
                uint32_t rB = (uint32_t)(wn*32 + nb*8 + g)*128;
                bh[nb][0] = lds32(tb + 2*16384 + rB + (o0^swz));
                bh[nb][1] = lds32(tb + 2*16384 + rB + ((o0+16)^swz));
                bl[nb][0] = lds32(tb + 3*16384 + rB + (o0^swz));
                bl[nb][1] = lds32(tb + 3*16384 + rB + ((o0+16)^swz));
            }
            #pragma unroll
            for (int mb = 0; mb < 4; mb++)
                #pragma unroll
                for (int nb = 0; nb < 4; nb++) {
                    mma16816(acc[mb][nb], ah[mb], bh[nb]);
                    mma16816(acc[mb][nb], ah[mb], bl[nb]);
                    mma16816(acc[mb][nb], al[mb], bh[nb]);
                }
        }
        __syncthreads();
    }

    #pragma unroll
    for (int mb = 0; mb < 4; mb++) {
        #pragma unroll
        for (int half = 0; half < 2; half++) {
            int row = brow + wm*64 + mb*16 + g + 8*half;
            #pragma unroll
            for (int nb = 0; nb < 4; nb++) {
                int col = bcol + wn*32 + nb*8 + 2*tig;
                float v0 = acc[mb][nb][2*half];
                float v1 = acc[mb][nb][2*half+1];
                if (bias) { v0 += bias[col]; v1 += bias[col+1]; }
                *(float2*)(Cf + (size_t)row * N + col) = make_float2(v0, v1);
            }
        }
    }
}

// ---------------------------------------------------------------------------
// RoPE (rotate-half), in place, fp32  (round-1 verbatim)
// ---------------------------------------------------------------------------
__global__ void rope_kernel(float* __restrict__ t, int nHeads, int total) {
    int idx = blockIdx.x * blockDim.x + threadIdx.x;
    if (idx >= total) return;
    int j = idx & 63;
    int h = (idx >> 6) % nHeads;
    int s = (idx / (64 * nHeads)) % SS;
    int b = idx / (64 * nHeads * SS);
    float inv_freq = expf(-((float)(2*j) / 128.f) * logf(10000.f));
    float ang = (float)s * inv_freq;
    float c, sn;
    sincosf(ang, &sn, &c);
    float* base = t + ((size_t)(b*SS + s) * nHeads + h) * 128;
    float a0 = base[j];
    float a1 = base[j + 64];
    base[j]      = a0 * c - a1 * sn;
    base[j + 64] = a1 * c + a0 * sn;
}

// ---------------------------------------------------------------------------
// Causal grouped flash attention, fp32 (round-1 verbatim)
// ---------------------------------------------------------------------------
__global__ __launch_bounds__(256, 4)
void attn_kernel(const float* __restrict__ q, const float* __restrict__ k,
                 const float* __restrict__ v, float* __restrict__ out) {
    int qt = blockIdx.x;
    int hq = blockIdx.y;
    int b  = blockIdx.z;
    int g  = hq >> 2;
    int q0 = qt * 32;

    __shared__ float Qs[32][129];
    __shared__ float KVs[32][129];

    int tid = threadIdx.x;
    int tx = tid & 31;
    int ty = tid >> 5;

    for (int i = tid; i < 32*32; i += 256) {
        int r = i >> 5;
        int c4 = (i & 31) * 4;
        float4 vq = *(const float4*)(q + (size_t)(b*SS + q0 + r) * QDIM + hq*128 + c4);
        Qs[r][c4+0] = vq.x; Qs[r][c4+1] = vq.y; Qs[r][c4+2] = vq.z; Qs[r][c4+3] = vq.w;
    }

    float m[4], l[4], acc[4][4];
    #pragma unroll
    for (int rr = 0; rr < 4; rr++) {
        m[rr] = -INFINITY; l[rr] = 0.f;
        #pragma unroll
        for (int cc = 0; cc < 4; cc++) acc[rr][cc] = 0.f;
    }

    const float scale = 0.08838834764831845f;

    for (int kt = 0; kt <= qt; kt++) {
        int n0 = kt * 32;
        __syncthreads();
        for (int i = tid; i < 32*32; i += 256) {
            int r = i >> 5;
            int c4 = (i & 31) * 4;
            float4 vk = *(const float4*)(k + (size_t)(b*SS + n0 + r) * KVDIM + g*128 + c4);
            KVs[r][c4+0] = vk.x; KVs[r][c4+1] = vk.y; KVs[r][c4+2] = vk.z; KVs[r][c4+3] = vk.w;
        }
        __syncthreads();

        float p[4];
        #pragma unroll
        for (int rr = 0; rr < 4; rr++) {
            int row = rr*8 + ty;
            float sc = 0.f;
            #pragma unroll 8
            for (int d = 0; d < 128; d++)
                sc += Qs[row][d] * KVs[tx][d];
            sc *= scale;
            int qi = q0 + row;
            int kj = n0 + tx;
            if (kj > qi) sc = -1e30f;
            float mx = sc;
            #pragma unroll
            for (int off = 16; off > 0; off >>= 1)
                mx = fmaxf(mx, __shfl_xor_sync(0xffffffffu, mx, off));
            float mnew = fmaxf(m[rr], mx);
            float alpha = __expf(m[rr] - mnew);
            float pv = __expf(sc - mnew);
            float rs = pv;
            #pragma unroll
            for (int off = 16; off > 0; off >>= 1)
                rs += __shfl_xor_sync(0xffffffffu, rs, off);
            l[rr] = l[rr] * alpha + rs;
            m[rr] = mnew;
            p[rr] = pv;
            #pragma unroll
            for (int cc = 0; cc < 4; cc++) acc[rr][cc] *= alpha;
        }

        __syncthreads();
        for (int i = tid; i < 32*32; i += 256) {
            int r = i >> 5;
            int c4 = (i & 31) * 4;
            float4 vv = *(const float4*)(v + (size_t)(b*SS + n0 + r) * KVDIM + g*128 + c4);
            KVs[r][c4+0] = vv.x; KVs[r][c4+1] = vv.y; KVs[r][c4+2] = vv.z; KVs[r][c4+3] = vv.w;
        }
        __syncthreads();

        #pragma unroll 8
        for (int j = 0; j < 32; j++) {
            float v0 = KVs[j][tx];
            float v1 = KVs[j][tx + 32];
            float v2 = KVs[j][tx + 64];
            float v3 = KVs[j][tx + 96];
            #pragma unroll
            for (int rr = 0; rr < 4; rr++) {
                float pj = __shfl_sync(0xffffffffu, p[rr], j);
                acc[rr][0] += pj * v0;
                acc[rr][1] += pj * v1;
                acc[rr][2] += pj * v2;
                acc[rr][3] += pj * v3;
            }
        }
    }

    #pragma unroll
    for (int rr = 0; rr < 4; rr++) {
        int row = rr*8 + ty;
        float invl = 1.f / l[rr];
        float* ob = out + (size_t)(b*SS + q0 + row) * QDIM + hq*128;
        #pragma unroll
        for (int cc = 0; cc < 4; cc++)
            ob[tx + cc*32] = acc[rr][cc] * invl;
    }
}

// ---------------------------------------------------------------------------
extern "C" void kernel_launch(void* const* d_in, const int* in_sizes, int n_in,
                              void* d_out, int out_size) {
    const float* x  = (const float*)d_in[0];
    const float* qp = (const float*)d_in[1];
    const float* kp = (const float*)d_in[2];
    const float* vp = (const float*)d_in[3];
    const float* qb = (const float*)d_in[4];
    const float* kb = (const float*)d_in[5];
    const float* vb = (const float*)d_in[6];
    const float* op = (const float*)d_in[7];
    const float* lw = (const float*)d_in[8];
    float* out = (float*)d_out;

    bf16 *hhi, *hlo, *wqh, *wql, *wkh, *wkl, *wvh, *wvl, *woh, *wol, *athi, *atlo;
    float *q, *k, *v, *att;
    cudaGetSymbolAddress((void**)&hhi, g_h_hi);
    cudaGetSymbolAddress((void**)&hlo, g_h_lo);
    cudaGetSymbolAddress((void**)&wqh, g_wq_hi);
    cudaGetSymbolAddress((void**)&wql, g_wq_lo);
    cudaGetSymbolAddress((void**)&wkh, g_wk_hi);
    cudaGetSymbolAddress((void**)&wkl, g_wk_lo);
    cudaGetSymbolAddress((void**)&wvh, g_wv_hi);
    cudaGetSymbolAddress((void**)&wvl, g_wv_lo);
    cudaGetSymbolAddress((void**)&woh, g_wo_hi);
    cudaGetSymbolAddress((void**)&wol, g_wo_lo);
    cudaGetSymbolAddress((void**)&athi, g_att_hi);
    cudaGetSymbolAddress((void**)&atlo, g_att_lo);
    cudaGetSymbolAddress((void**)&q, g_q);
    cudaGetSymbolAddress((void**)&k, g_k);
    cudaGetSymbolAddress((void**)&v, g_v);
    cudaGetSymbolAddress((void**)&att, g_att);

    cudaFuncSetAttribute(gemm_mma, cudaFuncAttributeMaxDynamicSharedMemorySize, 131072);

    // 0. split weights
    split_kernel<<<(QDIM*HID/4 + 255)/256, 256>>>(qp, wqh, wql, QDIM*HID/4);
    split_kernel<<<(KVDIM*HID/4 + 255)/256, 256>>>(kp, wkh, wkl, KVDIM*HID/4);
    split_kernel<<<(KVDIM*HID/4 + 255)/256, 256>>>(vp, wvh, wvl, KVDIM*HID/4);
    split_kernel<<<(HID*QDIM/4 + 255)/256, 256>>>(op, woh, wol, HID*QDIM/4);

    // 1. RMSNorm -> hi/lo
    rmsnorm_kernel<<<MM, 256>>>(x, lw, hhi, hlo);

    // 2. projections (HMMA, fp32 out)
    {
        dim3 gq(QDIM/128, MM/128);
        gemm_mma<<<gq, 256, 131072>>>(hhi, hlo, wqh, wql, qb, q, QDIM);
        dim3 gkv(KVDIM/128, MM/128);
        gemm_mma<<<gkv, 256, 131072>>>(hhi, hlo, wkh, wkl, kb, k, KVDIM);
        gemm_mma<<<gkv, 256, 131072>>>(hhi, hlo, wvh, wvl, vb, v, KVDIM);
    }

    // 3. RoPE (fp32 in-place)
    {
        int totq = BB * SS * HQ * 64;
        rope_kernel<<<(totq + 255)/256, 256>>>(q, HQ, totq);
        int totk = BB * SS * HKV * 64;
        rope_kernel<<<(totk + 255)/256, 256>>>(k, HKV, totk);
    }

    // 4. attention (fp32, validated)
    {
        dim3 ga(SS/32, HQ, BB);
        attn_kernel<<<ga, 256>>>(q, k, v, att);
    }

    // 5. split att -> hi/lo, then O projection (HMMA) -> fp32 out
    split_kernel<<<(MM*QDIM/4 + 255)/256, 256>>>(att, athi, atlo, MM*QDIM/4);
    {
        dim3 go(HID/128, MM/128);
        gemm_mma<<<go, 256, 131072>>>(athi, atlo, woh, wol, nullptr, out, HID);
    }
}

// round 8
// speedup vs baseline: 3.3464x; 2.3011x over previous
#include <cuda_runtime.h>
#include <cuda_bf16.h>
#include <cstdint>
#include <math.h>

typedef __nv_bfloat16 bf16;

#define BB   2
#define SS   2048
#define HID  2048
#define HQ   16
#define HKV  4
#define MM   (BB*SS)          // 4096
#define QDIM 2048
#define KVDIM 512

// ---------------- scratch ----------------
__device__ __align__(16) bf16 g_h_hi[MM*HID];
__device__ __align__(16) bf16 g_h_lo[MM*HID];
__device__ __align__(16) bf16 g_wq_hi[QDIM*HID];
__device__ __align__(16) bf16 g_wq_lo[QDIM*HID];
__device__ __align__(16) bf16 g_wk_hi[KVDIM*HID];
__device__ __align__(16) bf16 g_wk_lo[KVDIM*HID];
__device__ __align__(16) bf16 g_wv_hi[KVDIM*HID];
__device__ __align__(16) bf16 g_wv_lo[KVDIM*HID];
__device__ __align__(16) bf16 g_wo_hi[HID*QDIM];
__device__ __align__(16) bf16 g_wo_lo[HID*QDIM];
__device__ __align__(16) float g_q[MM*QDIM];
__device__ __align__(16) float g_k[MM*KVDIM];
__device__ __align__(16) float g_v[MM*KVDIM];
__device__ __align__(16) bf16 g_qh[MM*QDIM];
__device__ __align__(16) bf16 g_ql[MM*QDIM];
__device__ __align__(16) bf16 g_kh[MM*KVDIM];
__device__ __align__(16) bf16 g_kl[MM*KVDIM];
__device__ __align__(16) float g_att[MM*QDIM];
__device__ __align__(16) bf16 g_att_hi[MM*QDIM];
__device__ __align__(16) bf16 g_att_lo[MM*QDIM];

// ---------------- helpers ----------------
__device__ __forceinline__ uint32_t smem_u32(const void* p) {
    uint32_t a;
    asm("{ .reg .u64 t; cvta.to.shared.u64 t, %1; cvt.u32.u64 %0, t; }" : "=r"(a) : "l"(p));
    return a;
}
__device__ __forceinline__ void cp16(uint32_t dst, const void* src) {
    asm volatile("cp.async.cg.shared.global [%0], [%1], 16;" :: "r"(dst), "l"(src));
}
#define CP_COMMIT() asm volatile("cp.async.commit_group;" ::: "memory")
#define CP_WAIT(n)  asm volatile("cp.async.wait_group %0;" :: "n"(n) : "memory")

// volatile + memory clobber: pinned in program order; never rematerialized
__device__ __forceinline__ uint32_t lds32(uint32_t a) {
    uint32_t v;
    asm volatile("ld.shared.b32 %0, [%1];" : "=r"(v) : "r"(a) : "memory");
    return v;
}
__device__ __forceinline__ void mma16816(float* d, const uint32_t* a, const uint32_t* b) {
    asm volatile("mma.sync.aligned.m16n8k16.row.col.f32.bf16.bf16.f32 "
        "{%0,%1,%2,%3}, {%4,%5,%6,%7}, {%8,%9}, {%0,%1,%2,%3};"
        : "+f"(d[0]), "+f"(d[1]), "+f"(d[2]), "+f"(d[3])
        : "r"(a[0]), "r"(a[1]), "r"(a[2]), "r"(a[3]), "r"(b[0]), "r"(b[1]));
}

// ---------------------------------------------------------------------------
// RMSNorm -> bf16 hi/lo (validated)
// ---------------------------------------------------------------------------
__global__ void rmsnorm_kernel(const float* __restrict__ x,
                               const float* __restrict__ w,
                               bf16* __restrict__ ohi, bf16* __restrict__ olo) {
    int row = blockIdx.x;
    int tid = threadIdx.x;
    const float4* xr = (const float4*)(x + (size_t)row * HID);
    float4 a = xr[tid];
    float4 b = xr[tid + 256];
    float ss = a.x*a.x + a.y*a.y + a.z*a.z + a.w*a.w
             + b.x*b.x + b.y*b.y + b.z*b.z + b.w*b.w;
    #pragma unroll
    for (int off = 16; off > 0; off >>= 1)
        ss += __shfl_xor_sync(0xffffffffu, ss, off);
    __shared__ float sred[8];
    __shared__ float sinv;
    if ((tid & 31) == 0) sred[tid >> 5] = ss;
    __syncthreads();
    if (tid == 0) {
        float t = 0.f;
        #pragma unroll
        for (int i = 0; i < 8; i++) t += sred[i];
        sinv = rsqrtf(t / (float)HID + 1e-6f);
    }
    __syncthreads();
    float inv = sinv;
    const float4* wr = (const float4*)w;
    float4 wa = wr[tid], wb = wr[tid + 256];
    float va[8] = { a.x*inv*wa.x, a.y*inv*wa.y, a.z*inv*wa.z, a.w*inv*wa.w,
                    b.x*inv*wb.x, b.y*inv*wb.y, b.z*inv*wb.z, b.w*inv*wb.w };
    size_t base0 = (size_t)row * HID + tid*4;
    size_t base1 = (size_t)row * HID + (tid+256)*4;
    #pragma unroll
    for (int i = 0; i < 4; i++) {
        bf16 h0 = __float2bfloat16(va[i]);
        ohi[base0+i] = h0;
        olo[base0+i] = __float2bfloat16(va[i] - __bfloat162float(h0));
        bf16 h1 = __float2bfloat16(va[4+i]);
        ohi[base1+i] = h1;
        olo[base1+i] = __float2bfloat16(va[4+i] - __bfloat162float(h1));
    }
}

// ---------------------------------------------------------------------------
// split fp32 -> bf16 hi/lo (validated)
// ---------------------------------------------------------------------------
__global__ void split_kernel(const float* __restrict__ in, bf16* __restrict__ hi,
                             bf16* __restrict__ lo, int n4) {
    int i = blockIdx.x * 256 + threadIdx.x;
    if (i >= n4) return;
    float4 v = ((const float4*)in)[i];
    bf16 h0 = __float2bfloat16(v.x), h1 = __float2bfloat16(v.y);
    bf16 h2 = __float2bfloat16(v.z), h3 = __float2bfloat16(v.w);
    __nv_bfloat162 hh0; hh0.x = h0; hh0.y = h1;
    __nv_bfloat162 hh1; hh1.x = h2; hh1.y = h3;
    __nv_bfloat162 ll0, ll1;
    ll0.x = __float2bfloat16(v.x - __bfloat162float(h0));
    ll0.y = __float2bfloat16(v.y - __bfloat162float(h1));
    ll1.x = __float2bfloat16(v.z - __bfloat162float(h2));
    ll1.y = __float2bfloat16(v.w - __bfloat162float(h3));
    ((__nv_bfloat162*)hi)[i*2+0] = hh0;
    ((__nv_bfloat162*)hi)[i*2+1] = hh1;
    ((__nv_bfloat162*)lo)[i*2+0] = ll0;
    ((__nv_bfloat162*)lo)[i*2+1] = ll1;
}

// ---------------------------------------------------------------------------
// HMMA GEMM (NT) — validated (round-5 verbatim, fp32 epilogue).
// ---------------------------------------------------------------------------
__global__ __launch_bounds__(256, 1)
void gemm_mma(const bf16* __restrict__ Ah, const bf16* __restrict__ Al,
              const bf16* __restrict__ Bh, const bf16* __restrict__ Bl,
              const float* __restrict__ bias, float* __restrict__ Cf, int N) {
    extern __shared__ __align__(128) char sm[];
    uint32_t sb = smem_u32(sm);
    int tid = threadIdx.x;
    int w = tid >> 5, lane = tid & 31, g = lane >> 2, tig = lane & 3;
    int wm = w & 1, wn = w >> 1;
    int brow = blockIdx.y * 128, bcol = blockIdx.x * 128;

    float acc[4][4][4];
    #pragma unroll
    for (int a = 0; a < 4; a++)
        #pragma unroll
        for (int b = 0; b < 4; b++)
            #pragma unroll
            for (int c = 0; c < 4; c++) acc[a][b][c] = 0.f;

    auto load_stage = [&](int s, int ck) {
        #pragma unroll
        for (int mat = 0; mat < 4; mat++) {
            const bf16* base = (mat == 0) ? Ah : (mat == 1) ? Al : (mat == 2) ? Bh : Bl;
            int ro = (mat < 2) ? brow : bcol;
            #pragma unroll
            for (int i = 0; i < 4; i++) {
                int id = i*256 + tid;
                int r = id >> 3, c = id & 7;
                cp16(sb + s*65536 + mat*16384 + r*128 + (((uint32_t)c*16) ^ ((uint32_t)(r&7)*16)),
                     base + (size_t)(ro + r)*2048 + ck*64 + c*8);
            }
        }
    };

    load_stage(0, 0);
    CP_COMMIT();

    for (int ck = 0; ck < 32; ck++) {
        if (ck + 1 < 32) { load_stage((ck+1)&1, ck+1); CP_COMMIT(); CP_WAIT(1); }
        else             { CP_WAIT(0); }
        __syncthreads();
        uint32_t tb = sb + (ck&1)*65536;
        uint32_t swz = (uint32_t)g*16;
        #pragma unroll
        for (int ks = 0; ks < 4; ks++) {
            uint32_t o0 = (uint32_t)(32*ks + 4*tig);
            uint32_t ah[4][4], al[4][4];
            #pragma unroll
            for (int mb = 0; mb < 4; mb++) {
                uint32_t r0 = (uint32_t)(wm*64 + mb*16 + g)*128;
                uint32_t r1 = r0 + 8*128;
                ah[mb][0] = lds32(tb + r0 + (o0^swz));
                ah[mb][1] = lds32(tb + r1 + (o0^swz));
                ah[mb][2] = lds32(tb + r0 + ((o0+16)^swz));
                ah[mb][3] = lds32(tb + r1 + ((o0+16)^swz));
                al[mb][0] = lds32(tb + 16384 + r0 + (o0^swz));
                al[mb][1] = lds32(tb + 16384 + r1 + (o0^swz));
                al[mb][2] = lds32(tb + 16384 + r0 + ((o0+16)^swz));
                al[mb][3] = lds32(tb + 16384 + r1 + ((o0+16)^swz));
            }
            uint32_t bh[4][2], bl[4][2];
            #pragma unroll
            for (int nb = 0; nb < 4; nb++) {
                uint32_t rB = (uint32_t)(wn*32 + nb*8 + g)*128;
                bh[nb][0] = lds32(tb + 2*16384 + rB + (o0^swz));
                bh[nb][1] = lds32(tb + 2*16384 + rB + ((o0+16)^swz));
                bl[nb][0] = lds32(tb + 3*16384 + rB + (o0^swz));
                bl[nb][1] = lds32(tb + 3*16384 + rB + ((o0+16)^swz));
            }
            #pragma unroll
            for (int mb = 0; mb < 4; mb++)
                #pragma unroll
                for (int nb = 0; nb < 4; nb++) {
                    mma16816(acc[mb][nb], ah[mb], bh[nb]);
                    mma16816(acc[mb][nb], ah[mb], bl[nb]);
                    mma16816(acc[mb][nb], al[mb], bh[nb]);
                }
        }
        __syncthreads();
    }

    #pragma unroll
    for (int mb = 0; mb < 4; mb++) {
        #pragma unroll
        for (int half = 0; half < 2; half++) {
            int row = brow + wm*64 + mb*16 + g + 8*half;
            #pragma unroll
            for (int nb = 0; nb < 4; nb++) {
                int col = bcol + wn*32 + nb*8 + 2*tig;
                float v0 = acc[mb][nb][2*half];
                float v1 = acc[mb][nb][2*half+1];
                if (bias) { v0 += bias[col]; v1 += bias[col+1]; }
                *(float2*)(Cf + (size_t)row * N + col) = make_float2(v0, v1);
            }
        }
    }
}

// ---------------------------------------------------------------------------
// RoPE: fp32 in -> bf16 hi/lo out
// ---------------------------------------------------------------------------
__global__ void rope_split_kernel(const float* __restrict__ t,
                                  bf16* __restrict__ oh, bf16* __restrict__ ol,
                                  int nHeads, int total) {
    int idx = blockIdx.x * blockDim.x + threadIdx.x;
    if (idx >= total) return;
    int j = idx & 63;
    int h = (idx >> 6) % nHeads;
    int s = (idx / (64 * nHeads)) % SS;
    int b = idx / (64 * nHeads * SS);
    float inv_freq = expf(-((float)(2*j) / 128.f) * logf(10000.f));
    float ang = (float)s * inv_freq;
    float c, sn;
    sincosf(ang, &sn, &c);
    size_t base = ((size_t)(b*SS + s) * nHeads + h) * 128;
    float a0 = t[base + j];
    float a1 = t[base + j + 64];
    float r0 = a0 * c - a1 * sn;
    float r1 = a1 * c + a0 * sn;
    bf16 h0 = __float2bfloat16(r0);
    oh[base + j] = h0;
    ol[base + j] = __float2bfloat16(r0 - __bfloat162float(h0));
    bf16 h1 = __float2bfloat16(r1);
    oh[base + j + 64] = h1;
    ol[base + j + 64] = __float2bfloat16(r1 - __bfloat162float(h1));
}

// ---------------------------------------------------------------------------
// Attention: HMMA S = QK^T (3-term hi/lo) + register softmax + fp32 PV.
// 128 threads (4 warps), BM=64 (16 rows/warp), BN=64, D=128.
// smem (dynamic 116736 B) — Q has its OWN region, never overwritten:
//   [0]      Qh 16KB : [d-half][row 64][128B]
//   [16384]  Ql 16KB
//   [32768]  Kh 16KB : [d-half][key 64][128B]
//   [49152]  Kl 16KB
//   [65536]  Vs fp32 : 64 key-rows x 132 floats (528B stride)
//   [99328]  Ps fp32 : 64 q-rows x 68 floats (272B stride)
// ---------------------------------------------------------------------------
#define KH_OFF 32768
#define VS_OFF 65536
#define PS_OFF 99328
#define ATTN_SMEM 116736

__global__ __launch_bounds__(128)
void attn_smma(const bf16* __restrict__ qh, const bf16* __restrict__ ql,
               const bf16* __restrict__ kh, const bf16* __restrict__ kl,
               const float* __restrict__ v, float* __restrict__ out) {
    extern __shared__ __align__(128) char sm[];
    uint32_t sb = smem_u32(sm);
    int tid = threadIdx.x, w = tid >> 5, lane = tid & 31, g = lane >> 2, tig = lane & 3;
    int qt = gridDim.x - 1 - blockIdx.x;
    int hq = blockIdx.y, b = blockIdx.z, gkv = hq >> 2;
    int q0 = qt * 64;
    uint32_t swz = (uint32_t)g*16;
    int row0 = w*16 + g, row1 = row0 + 8;

    // ---- stage Q hi/lo into dedicated regions 0/1 ----
    #pragma unroll
    for (int mat = 0; mat < 2; mat++) {
        const bf16* src = mat ? ql : qh;
        #pragma unroll
        for (int i = 0; i < 8; i++) {
            int id = i*128 + tid;
            int r = id >> 4, c = id & 15;
            cp16(sb + mat*16384 + (c>>3)*8192 + r*128 + (((uint32_t)(c&7)*16) ^ ((uint32_t)(r&7)*16)),
                 src + ((size_t)((b*SS + q0 + r)*HQ + hq))*128 + c*8);
        }
    }
    CP_COMMIT(); CP_WAIT(0);
    __syncthreads();

    // O accumulators
    float o0a[32], o1a[32];
    #pragma unroll
    for (int i = 0; i < 32; i++) { o0a[i] = 0.f; o1a[i] = 0.f; }
    float m0 = -INFINITY, m1 = -INFINITY, l0 = 0.f, l1 = 0.f;
    const float scale = 0.08838834764831845f;

    for (int kt = 0; kt <= qt; kt++) {
        int n0 = kt * 64;
        __syncthreads();
        // K hi/lo -> dedicated K regions
        #pragma unroll
        for (int mat = 0; mat < 2; mat++) {
            const bf16* base = mat ? kl : kh;
            #pragma unroll
            for (int i = 0; i < 8; i++) {
                int id = i*128 + tid;
                int r = id >> 4, c = id & 15;
                cp16(sb + KH_OFF + mat*16384 + (c>>3)*8192 + r*128 + (((uint32_t)(c&7)*16) ^ ((uint32_t)(r&7)*16)),
                     base + ((size_t)((b*SS + n0 + r)*HKV + gkv))*128 + c*8);
            }
        }
        // V fp32
        #pragma unroll
        for (int i = 0; i < 16; i++) {
            int id = i*128 + tid;
            int r = id >> 5, c = id & 31;
            cp16(sb + VS_OFF + (uint32_t)r*528 + (uint32_t)c*16,
                 v + (size_t)(b*SS + n0 + r)*KVDIM + gkv*128 + c*4);
        }
        CP_COMMIT(); CP_WAIT(0);
        __syncthreads();

        // ---- S = Q K^T (3-term); Q frags loaded in-loop from dedicated region ----
        float sacc[8][4];
        #pragma unroll
        for (int nb = 0; nb < 8; nb++)
            #pragma unroll
            for (int c = 0; c < 4; c++) sacc[nb][c] = 0.f;
        #pragma unroll
        for (int kb = 0; kb < 8; kb++) {
            uint32_t half = (uint32_t)(kb>>2)*8192;
            uint32_t o0 = (uint32_t)((kb&3)*32 + 4*tig);
            uint32_t r0a = (uint32_t)row0*128, r1a = r0a + 8*128;
            uint32_t qhf[4], qlf[4];
            qhf[0] = lds32(sb + half + r0a + (o0^swz));
            qhf[1] = lds32(sb + half + r1a + (o0^swz));
            qhf[2] = lds32(sb + half + r0a + ((o0+16)^swz));
            qhf[3] = lds32(sb + half + r1a + ((o0+16)^swz));
            qlf[0] = lds32(sb + 16384 + half + r0a + (o0^swz));
            qlf[1] = lds32(sb + 16384 + half + r1a + (o0^swz));
            qlf[2] = lds32(sb + 16384 + half + r0a + ((o0+16)^swz));
            qlf[3] = lds32(sb + 16384 + half + r1a + ((o0+16)^swz));
            #pragma unroll
            for (int nb = 0; nb < 8; nb++) {
                uint32_t rB = (uint32_t)(nb*8 + g)*128;
                uint32_t bhf[2], blf[2];
                bhf[0] = lds32(sb + KH_OFF + half + rB + (o0^swz));
                bhf[1] = lds32(sb + KH_OFF + half + rB + ((o0+16)^swz));
                blf[0] = lds32(sb + KH_OFF + 16384 + half + rB + (o0^swz));
                blf[1] = lds32(sb + KH_OFF + 16384 + half + rB + ((o0+16)^swz));
                mma16816(sacc[nb], qhf, bhf);
                mma16816(sacc[nb], qhf, blf);
                mma16816(sacc[nb], qlf, bhf);
            }
        }

        // ---- online softmax ----
        #pragma unroll
        for (int nb = 0; nb < 8; nb++)
            #pragma unroll
            for (int c = 0; c < 4; c++) sacc[nb][c] *= scale;
        if (kt == qt) {
            #pragma unroll
            for (int nb = 0; nb < 8; nb++) {
                int col0 = nb*8 + 2*tig;
                if (col0     > row0) sacc[nb][0] = -INFINITY;
                if (col0 + 1 > row0) sacc[nb][1] = -INFINITY;
                if (col0     > row1) sacc[nb][2] = -INFINITY;
                if (col0 + 1 > row1) sacc[nb][3] = -INFINITY;
            }
        }
        float mx0 = -INFINITY, mx1 = -INFINITY;
        #pragma unroll
        for (int nb = 0; nb < 8; nb++) {
            mx0 = fmaxf(mx0, fmaxf(sacc[nb][0], sacc[nb][1]));
            mx1 = fmaxf(mx1, fmaxf(sacc[nb][2], sacc[nb][3]));
        }
        mx0 = fmaxf(mx0, __shfl_xor_sync(0xffffffffu, mx0, 1));
        mx0 = fmaxf(mx0, __shfl_xor_sync(0xffffffffu, mx0, 2));
        mx1 = fmaxf(mx1, __shfl_xor_sync(0xffffffffu, mx1, 1));
        mx1 = fmaxf(mx1, __shfl_xor_sync(0xffffffffu, mx1, 2));
        float mn0 = fmaxf(m0, mx0), mn1 = fmaxf(m1, mx1);
        float al0 = __expf(m0 - mn0), al1 = __expf(m1 - mn1);
        float rs0 = 0.f, rs1 = 0.f;
        #pragma unroll
        for (int nb = 0; nb < 8; nb++) {
            sacc[nb][0] = __expf(sacc[nb][0] - mn0); rs0 += sacc[nb][0];
            sacc[nb][1] = __expf(sacc[nb][1] - mn0); rs0 += sacc[nb][1];
            sacc[nb][2] = __expf(sacc[nb][2] - mn1); rs1 += sacc[nb][2];
            sacc[nb][3] = __expf(sacc[nb][3] - mn1); rs1 += sacc[nb][3];
        }
        rs0 += __shfl_xor_sync(0xffffffffu, rs0, 1);
        rs0 += __shfl_xor_sync(0xffffffffu, rs0, 2);
        rs1 += __shfl_xor_sync(0xffffffffu, rs1, 1);
        rs1 += __shfl_xor_sync(0xffffffffu, rs1, 2);
        l0 = l0*al0 + rs0; l1 = l1*al1 + rs1;
        m0 = mn0; m1 = mn1;
        #pragma unroll
        for (int i = 0; i < 32; i++) { o0a[i] *= al0; o1a[i] *= al1; }

        // ---- P -> smem fp32 (plain row-major) ----
        #pragma unroll
        for (int nb = 0; nb < 8; nb++) {
            uint32_t cb = (uint32_t)(nb*8 + 2*tig)*4;
            *(volatile float*)(sm + PS_OFF + (uint32_t)row0*272 + cb)     = sacc[nb][0];
            *(volatile float*)(sm + PS_OFF + (uint32_t)row0*272 + cb + 4) = sacc[nb][1];
            *(volatile float*)(sm + PS_OFF + (uint32_t)row1*272 + cb)     = sacc[nb][2];
            *(volatile float*)(sm + PS_OFF + (uint32_t)row1*272 + cb + 4) = sacc[nb][3];
        }
        __syncwarp();

        // ---- O += P V (fp32 scalar; warp-private P rows) ----
        #pragma unroll 4
        for (int key = 0; key < 64; key++) {
            float p0 = *(volatile const float*)(sm + PS_OFF + (uint32_t)row0*272 + (uint32_t)key*4);
            float p1 = *(volatile const float*)(sm + PS_OFF + (uint32_t)row1*272 + (uint32_t)key*4);
            #pragma unroll
            for (int j4 = 0; j4 < 8; j4++) {
                float4 vv = *(const float4*)(sm + VS_OFF + (uint32_t)key*528
                                             + (uint32_t)(j4*16 + tig*4)*4);
                o0a[j4*4+0] += p0*vv.x; o0a[j4*4+1] += p0*vv.y;
                o0a[j4*4+2] += p0*vv.z; o0a[j4*4+3] += p0*vv.w;
                o1a[j4*4+0] += p1*vv.x; o1a[j4*4+1] += p1*vv.y;
                o1a[j4*4+2] += p1*vv.z; o1a[j4*4+3] += p1*vv.w;
            }
        }
    }

    // ---- epilogue: normalize, write fp32 ----
    float inv0 = 1.f / l0, inv1 = 1.f / l1;
    float* ob0 = out + (size_t)(b*SS + q0 + row0)*QDIM + hq*128;
    float* ob1 = out + (size_t)(b*SS + q0 + row1)*QDIM + hq*128;
    #pragma unroll
    for (int j4 = 0; j4 < 8; j4++) {
        #pragma unroll
        for (int jj = 0; jj < 4; jj++) {
            int d = j4*16 + tig*4 + jj;
            ob0[d] = o0a[j4*4+jj] * inv0;
            ob1[d] = o1a[j4*4+jj] * inv1;
        }
    }
}

// ---------------------------------------------------------------------------
extern "C" void kernel_launch(void* const* d_in, const int* in_sizes, int n_in,
                              void* d_out, int out_size) {
    const float* x  = (const float*)d_in[0];
    const float* qp = (const float*)d_in[1];
    const float* kp = (const float*)d_in[2];
    const float* vp = (const float*)d_in[3];
    const float* qb = (const float*)d_in[4];
    const float* kb = (const float*)d_in[5];
    const float* vb = (const float*)d_in[6];
    const float* op = (const float*)d_in[7];
    const float* lw = (const float*)d_in[8];
    float* out = (float*)d_out;

    bf16 *hhi, *hlo, *wqh, *wql, *wkh, *wkl, *wvh, *wvl, *woh, *wol;
    bf16 *qhp, *qlp, *khp, *klp, *athi, *atlo;
    float *q, *k, *v, *att;
    cudaGetSymbolAddress((void**)&hhi, g_h_hi);
    cudaGetSymbolAddress((void**)&hlo, g_h_lo);
    cudaGetSymbolAddress((void**)&wqh, g_wq_hi);
    cudaGetSymbolAddress((void**)&wql, g_wq_lo);
    cudaGetSymbolAddress((void**)&wkh, g_wk_hi);
    cudaGetSymbolAddress((void**)&wkl, g_wk_lo);
    cudaGetSymbolAddress((void**)&wvh, g_wv_hi);
    cudaGetSymbolAddress((void**)&wvl, g_wv_lo);
    cudaGetSymbolAddress((void**)&woh, g_wo_hi);
    cudaGetSymbolAddress((void**)&wol, g_wo_lo);
    cudaGetSymbolAddress((void**)&qhp, g_qh);
    cudaGetSymbolAddress((void**)&qlp, g_ql);
    cudaGetSymbolAddress((void**)&khp, g_kh);
    cudaGetSymbolAddress((void**)&klp, g_kl);
    cudaGetSymbolAddress((void**)&athi, g_att_hi);
    cudaGetSymbolAddress((void**)&atlo, g_att_lo);
    cudaGetSymbolAddress((void**)&q, g_q);
    cudaGetSymbolAddress((void**)&k, g_k);
    cudaGetSymbolAddress((void**)&v, g_v);
    cudaGetSymbolAddress((void**)&att, g_att);

    cudaFuncSetAttribute(gemm_mma, cudaFuncAttributeMaxDynamicSharedMemorySize, 131072);
    cudaFuncSetAttribute(attn_smma, cudaFuncAttributeMaxDynamicSharedMemorySize, ATTN_SMEM);

    // 0. split weights (validated)
    split_kernel<<<(QDIM*HID/4 + 255)/256, 256>>>(qp, wqh, wql, QDIM*HID/4);
    split_kernel<<<(KVDIM*HID/4 + 255)/256, 256>>>(kp, wkh, wkl, KVDIM*HID/4);
    split_kernel<<<(KVDIM*HID/4 + 255)/256, 256>>>(vp, wvh, wvl, KVDIM*HID/4);
    split_kernel<<<(HID*QDIM/4 + 255)/256, 256>>>(op, woh, wol, HID*QDIM/4);

    // 1. RMSNorm -> hi/lo (validated)
    rmsnorm_kernel<<<MM, 256>>>(x, lw, hhi, hlo);

    // 2. projections (validated gemm, fp32 out)
    {
        dim3 gq(QDIM/128, MM/128);
        gemm_mma<<<gq, 256, 131072>>>(hhi, hlo, wqh, wql, qb, q, QDIM);
        dim3 gkv(KVDIM/128, MM/128);
        gemm_mma<<<gkv, 256, 131072>>>(hhi, hlo, wkh, wkl, kb, k, KVDIM);
        gemm_mma<<<gkv, 256, 131072>>>(hhi, hlo, wvh, wvl, vb, v, KVDIM);
    }

    // 3. RoPE -> hi/lo
    {
        int totq = BB * SS * HQ * 64;
        rope_split_kernel<<<(totq + 255)/256, 256>>>(q, qhp, qlp, HQ, totq);
        int totk = BB * SS * HKV * 64;
        rope_split_kernel<<<(totk + 255)/256, 256>>>(k, khp, klp, HKV, totk);
    }

    // 4. attention: HMMA S + fp32 PV -> fp32 att
    {
        dim3 ga(SS/64, HQ, BB);
        attn_smma<<<ga, 128, ATTN_SMEM>>>(qhp, qlp, khp, klp, v, att);
    }

    // 5. split att -> hi/lo, O projection (validated chain)
    split_kernel<<<(MM*QDIM/4 + 255)/256, 256>>>(att, athi, atlo, MM*QDIM/4);
    {
        dim3 go(HID/128, MM/128);
        gemm_mma<<<go, 256, 131072>>>(athi, atlo, woh, wol, nullptr, out, HID);
    }
}